// round 12
// baseline (speedup 1.0000x reference)
#include <cuda_runtime.h>
#include <cuda_bf16.h>
#include <cstdint>

#define N_NODES 1000000
#define N_EDGES 8000000
#define NEG_SLOPE 0.01f
#define EPS_F 1e-10f
#define SCAN_NB ((N_NODES + 1023) / 1024)   // 977

// ---------------- static device scratch (no allocation allowed) --------------
__device__ float g_h[(size_t)N_NODES * 64];   // projected h: [node][64], ch0 cols 0-31, ch1 cols 32-63
__device__ int   g_cnt[N_NODES];              // edge count per destination row
__device__ int   g_off[N_NODES + 1];          // CSR offsets (exclusive scan of cnt)
__device__ int   g_cur[N_NODES];              // write cursors (init = off)
__device__ int   g_scol[N_EDGES];             // edge src (col) sorted by destination row
__device__ int   g_bsum[1024];                // scan block sums

// ---------------- helpers ----------------------------------------------------
__device__ __forceinline__ float leaky(float v) { return v > 0.f ? v : NEG_SLOPE * v; }

__device__ __forceinline__ void fma_f32x2(unsigned long long& d,
                                          unsigned long long a,
                                          unsigned long long b) {
    asm("fma.rn.f32x2 %0, %1, %2, %0;" : "+l"(d) : "l"(a), "l"(b));
}
__device__ __forceinline__ unsigned long long pack2(float x, float y) {
    unsigned long long r;
    asm("mov.b64 %0, {%1, %2};" : "=l"(r) : "f"(x), "f"(y));
    return r;
}
__device__ __forceinline__ float2 unpack2(unsigned long long v) {
    float2 r;
    asm("mov.b64 {%0, %1}, %2;" : "=f"(r.x), "=f"(r.y) : "l"(v));
    return r;
}

__device__ __forceinline__ int warp_incl_scan(int v) {
    #pragma unroll
    for (int s = 1; s < 32; s <<= 1) {
        int n = __shfl_up_sync(0xffffffffu, v, s);
        if ((threadIdx.x & 31) >= s) v += n;
    }
    return v;
}

// ---------------- kernel 0: zero counters ------------------------------------
__global__ void zero_kernel() {
    int i = blockIdx.x * blockDim.x + threadIdx.x;
    int stride = gridDim.x * blockDim.x;
    int4* c4 = (int4*)g_cnt;
    int4 z = make_int4(0, 0, 0, 0);
    for (int j = i; j < N_NODES / 4; j += stride) c4[j] = z;
    if (i == 0) g_off[N_NODES] = N_EDGES;
}

// ---------------- kernel 1: projection  h = leaky(ego @ W + b) ---------------
__global__ void project_kernel(const float* __restrict__ ego,
                               const float* __restrict__ W,
                               const float* __restrict__ b) {
    __shared__ unsigned long long Ws2[64 * 32];   // (W0[k][j], W1[k][j])
    __shared__ unsigned long long Bs2[32];
    int t = threadIdx.x;
    for (int idx = t; idx < 64 * 32; idx += blockDim.x) {
        int k = idx >> 5, j = idx & 31;
        Ws2[idx] = pack2(W[k * 32 + j], W[2048 + k * 32 + j]);
    }
    if (t < 32) Bs2[t] = pack2(b[t], b[32 + t]);
    __syncthreads();

    int lane = t & 31;
    int warp = (blockIdx.x * blockDim.x + t) >> 5;
    int nwarps = (gridDim.x * blockDim.x) >> 5;
    for (int base = warp * 4; base < N_NODES; base += nwarps * 4) {
        float2 e0 = *(const float2*)(ego + (size_t)(base + 0) * 64 + 2 * lane);
        float2 e1 = *(const float2*)(ego + (size_t)(base + 1) * 64 + 2 * lane);
        float2 e2 = *(const float2*)(ego + (size_t)(base + 2) * 64 + 2 * lane);
        float2 e3 = *(const float2*)(ego + (size_t)(base + 3) * 64 + 2 * lane);
        unsigned long long a0 = Bs2[lane], a1 = a0, a2 = a0, a3 = a0;
        #pragma unroll
        for (int k = 0; k < 64; k++) {
            unsigned long long wv = Ws2[k * 32 + lane];
            float s0 = __shfl_sync(0xffffffffu, (k & 1) ? e0.y : e0.x, k >> 1);
            float s1 = __shfl_sync(0xffffffffu, (k & 1) ? e1.y : e1.x, k >> 1);
            float s2 = __shfl_sync(0xffffffffu, (k & 1) ? e2.y : e2.x, k >> 1);
            float s3 = __shfl_sync(0xffffffffu, (k & 1) ? e3.y : e3.x, k >> 1);
            fma_f32x2(a0, pack2(s0, s0), wv);
            fma_f32x2(a1, pack2(s1, s1), wv);
            fma_f32x2(a2, pack2(s2, s2), wv);
            fma_f32x2(a3, pack2(s3, s3), wv);
        }
        float2 r0 = unpack2(a0), r1 = unpack2(a1), r2 = unpack2(a2), r3 = unpack2(a3);
        g_h[(size_t)(base + 0) * 64 + lane]      = leaky(r0.x);
        g_h[(size_t)(base + 0) * 64 + 32 + lane] = leaky(r0.y);
        g_h[(size_t)(base + 1) * 64 + lane]      = leaky(r1.x);
        g_h[(size_t)(base + 1) * 64 + 32 + lane] = leaky(r1.y);
        g_h[(size_t)(base + 2) * 64 + lane]      = leaky(r2.x);
        g_h[(size_t)(base + 2) * 64 + 32 + lane] = leaky(r2.y);
        g_h[(size_t)(base + 3) * 64 + lane]      = leaky(r3.x);
        g_h[(size_t)(base + 3) * 64 + 32 + lane] = leaky(r3.y);
    }
}

// ---------------- kernel 2: histogram of destination rows (int4 reads) -------
__global__ void hist_kernel(const int* __restrict__ row) {
    const int4* row4 = (const int4*)row;
    int i = blockIdx.x * blockDim.x + threadIdx.x;
    int stride = gridDim.x * blockDim.x;
    for (; i < N_EDGES / 4; i += stride) {
        int4 v = row4[i];
        atomicAdd(&g_cnt[v.x], 1);
        atomicAdd(&g_cnt[v.y], 1);
        atomicAdd(&g_cnt[v.z], 1);
        atomicAdd(&g_cnt[v.w], 1);
    }
}

// ---------------- kernels 3-5: exclusive scan of g_cnt -> g_off, g_cur -------
__global__ void scan1_kernel() {
    __shared__ int wsum[32];
    int t = threadIdx.x;
    int i = blockIdx.x * 1024 + t;
    int v = (i < N_NODES) ? g_cnt[i] : 0;
    int incl = warp_incl_scan(v);
    int wid = t >> 5, lid = t & 31;
    if (lid == 31) wsum[wid] = incl;
    __syncthreads();
    if (wid == 0) {
        int w = wsum[lid];
        int ws = warp_incl_scan(w);
        wsum[lid] = ws - w;
    }
    __syncthreads();
    int excl = incl - v + wsum[wid];
    if (i < N_NODES) g_off[i] = excl;
    if (t == 1023) g_bsum[blockIdx.x] = excl + v;
}

__global__ void scan2_kernel() {
    __shared__ int wsum[32];
    int t = threadIdx.x;
    int v = (t < SCAN_NB) ? g_bsum[t] : 0;
    int incl = warp_incl_scan(v);
    int wid = t >> 5, lid = t & 31;
    if (lid == 31) wsum[wid] = incl;
    __syncthreads();
    if (wid == 0) {
        int w = wsum[lid];
        int ws = warp_incl_scan(w);
        wsum[lid] = ws - w;
    }
    __syncthreads();
    int excl = incl - v + wsum[wid];
    if (t < SCAN_NB) g_bsum[t] = excl;
}

__global__ void scan3_kernel() {
    int i = blockIdx.x * 1024 + threadIdx.x;
    if (i < N_NODES) {
        int off = g_off[i] + g_bsum[blockIdx.x];
        g_off[i] = off;
        g_cur[i] = off;
    }
}

// ---------------- kernel 6: permute (counting sort of col, int4 reads) -------
__global__ void permute_kernel(const int* __restrict__ row, const int* __restrict__ col) {
    const int4* row4 = (const int4*)row;
    const int4* col4 = (const int4*)col;
    int i = blockIdx.x * blockDim.x + threadIdx.x;
    int stride = gridDim.x * blockDim.x;
    for (; i < N_EDGES / 4; i += stride) {
        int4 r = row4[i];
        int4 c = col4[i];
        g_scol[atomicAdd(&g_cur[r.x], 1)] = c.x;
        g_scol[atomicAdd(&g_cur[r.y], 1)] = c.y;
        g_scol[atomicAdd(&g_cur[r.z], 1)] = c.z;
        g_scol[atomicAdd(&g_cur[r.w], 1)] = c.w;
    }
}

// ---------------- kernel 7: fused logits + softmax + aggregation -------------
// EIGHT rows per warp: one 4-lane group per row. Lane s of a group holds
// ch0 floats [8s,8s+8) and ch1 floats [32+8s,32+8s+8) of its row (4 float4s).
// All 8 rows' setup loads are concurrent; per-iteration the warp gathers 8
// edges (8 x 256B coalesced). Warp-uniform trip count m = max deg of the 8
// rows; exhausted groups predicated (ex=0, clamped gather -> L1 hit).
// Depth-2 register prefetch. Each group writes its own row (no combine tail).
//   out = sum(ex*h_col) / (sum_ex + EPS)
__global__ void __launch_bounds__(256) row_kernel(float* __restrict__ out) {
    int t = blockIdx.x * blockDim.x + threadIdx.x;
    int lane = t & 31;
    int g = lane >> 2;                        // 0..7: row group
    int s = lane & 3;                         // lane within group
    int warp = t >> 5;
    int r = warp * 8 + g;                     // this group's row (< N_NODES always)

    int start = g_off[r];
    int deg   = g_off[r + 1] - start;
    // warp-uniform trip count: max degree over the 8 groups
    int m = deg;
    m = max(m, __shfl_xor_sync(0xffffffffu, m, 4));
    m = max(m, __shfl_xor_sync(0xffffffffu, m, 8));
    m = max(m, __shfl_xor_sync(0xffffffffu, m, 16));

    const float* hrp = g_h + (size_t)r * 64;
    const float4 hrA = *(const float4*)(hrp + 8 * s);
    const float4 hrB = *(const float4*)(hrp + 8 * s + 4);
    const float4 hrC = *(const float4*)(hrp + 32 + 8 * s);
    const float4 hrD = *(const float4*)(hrp + 36 + 8 * s);

    float se0 = 0.f, se1 = 0.f;
    float4 aA = make_float4(0.f, 0.f, 0.f, 0.f);
    float4 aB = make_float4(0.f, 0.f, 0.f, 0.f);
    float4 aC = make_float4(0.f, 0.f, 0.f, 0.f);
    float4 aD = make_float4(0.f, 0.f, 0.f, 0.f);

    if (m > 0) {
        // safe base for empty groups: read g_scol[0] (never out of bounds)
        int sbase  = (deg > 0) ? start : 0;
        int clampv = (deg > 0) ? deg - 1 : 0;

        int c = g_scol[sbase];
        const float* hp = g_h + (size_t)c * 64;
        float4 cA = *(const float4*)(hp + 8 * s);
        float4 cB = *(const float4*)(hp + 8 * s + 4);
        float4 cC = *(const float4*)(hp + 32 + 8 * s);
        float4 cD = *(const float4*)(hp + 36 + 8 * s);

        for (int k = 0; k < m; k++) {
            float4 pA, pB, pC, pD;
            if (k + 1 < m) {
                int kn = min(k + 1, clampv);
                int cn = g_scol[sbase + kn];
                const float* hq = g_h + (size_t)cn * 64;
                pA = *(const float4*)(hq + 8 * s);
                pB = *(const float4*)(hq + 8 * s + 4);
                pC = *(const float4*)(hq + 32 + 8 * s);
                pD = *(const float4*)(hq + 36 + 8 * s);
            }
            float d0 = hrA.x * cA.x + hrA.y * cA.y + hrA.z * cA.z + hrA.w * cA.w
                     + hrB.x * cB.x + hrB.y * cB.y + hrB.z * cB.z + hrB.w * cB.w;
            float d1 = hrC.x * cC.x + hrC.y * cC.y + hrC.z * cC.z + hrC.w * cC.w
                     + hrD.x * cD.x + hrD.y * cD.y + hrD.z * cD.z + hrD.w * cD.w;
            d0 += __shfl_xor_sync(0xffffffffu, d0, 2);
            d1 += __shfl_xor_sync(0xffffffffu, d1, 2);
            d0 += __shfl_xor_sync(0xffffffffu, d0, 1);
            d1 += __shfl_xor_sync(0xffffffffu, d1, 1);
            bool valid = (k < deg);
            float ex0 = valid ? __expf(leaky(d0)) : 0.f;
            float ex1 = valid ? __expf(leaky(d1)) : 0.f;
            se0 += ex0;
            se1 += ex1;
            aA.x += ex0 * cA.x; aA.y += ex0 * cA.y; aA.z += ex0 * cA.z; aA.w += ex0 * cA.w;
            aB.x += ex0 * cB.x; aB.y += ex0 * cB.y; aB.z += ex0 * cB.z; aB.w += ex0 * cB.w;
            aC.x += ex1 * cC.x; aC.y += ex1 * cC.y; aC.z += ex1 * cC.z; aC.w += ex1 * cC.w;
            aD.x += ex1 * cD.x; aD.y += ex1 * cD.y; aD.z += ex1 * cD.z; aD.w += ex1 * cD.w;
            cA = pA; cB = pB; cC = pC; cD = pD;
        }
    }

    float sc0 = 1.0f / (se0 + EPS_F);
    float sc1 = 1.0f / (se1 + EPS_F);
    float* op = out + (size_t)r * 64;
    *(float4*)(op + 8 * s)      = make_float4(aA.x * sc0, aA.y * sc0, aA.z * sc0, aA.w * sc0);
    *(float4*)(op + 8 * s + 4)  = make_float4(aB.x * sc0, aB.y * sc0, aB.z * sc0, aB.w * sc0);
    *(float4*)(op + 32 + 8 * s) = make_float4(aC.x * sc1, aC.y * sc1, aC.z * sc1, aC.w * sc1);
    *(float4*)(op + 36 + 8 * s) = make_float4(aD.x * sc1, aD.y * sc1, aD.z * sc1, aD.w * sc1);
}

// ---------------- launcher ---------------------------------------------------
// Two-stream fork: project_kernel runs concurrently with the
// zero->hist->scan->permute chain; both join before row_kernel.
static cudaStream_t g_s2 = nullptr;
static cudaEvent_t  g_ev_fork = nullptr;
static cudaEvent_t  g_ev_join = nullptr;

extern "C" void kernel_launch(void* const* d_in, const int* in_sizes, int n_in,
                              void* d_out, int out_size) {
    const float* ego = (const float*)d_in[0];   // [1M, 64] f32
    const float* W   = (const float*)d_in[1];   // [2, 64, 32] f32
    const float* b   = (const float*)d_in[2];   // [2, 1, 32] f32
    const int* row   = (const int*)d_in[3];     // [8M] i32 (destination)
    const int* col   = (const int*)d_in[4];     // [8M] i32 (source)
    float* out       = (float*)d_out;           // [1M, 64] f32

    if (g_s2 == nullptr) {
        cudaStreamCreateWithFlags(&g_s2, cudaStreamNonBlocking);
        cudaEventCreateWithFlags(&g_ev_fork, cudaEventDisableTiming);
        cudaEventCreateWithFlags(&g_ev_join, cudaEventDisableTiming);
    }

    // fork: side stream runs the projection concurrently
    cudaEventRecord(g_ev_fork, 0);
    cudaStreamWaitEvent(g_s2, g_ev_fork, 0);
    project_kernel<<<2048, 256, 0, g_s2>>>(ego, W, b);
    cudaEventRecord(g_ev_join, g_s2);

    // main stream: build sorted-edge structure
    zero_kernel<<<1024, 256>>>();
    hist_kernel<<<4096, 256>>>(row);
    scan1_kernel<<<SCAN_NB, 1024>>>();
    scan2_kernel<<<1, 1024>>>();
    scan3_kernel<<<SCAN_NB, 1024>>>();
    permute_kernel<<<4096, 256>>>(row, col);

    // join: row pass needs both g_h (projection) and g_scol/g_off (sort)
    cudaStreamWaitEvent(0, g_ev_join, 0);
    row_kernel<<<15625, 256>>>(out);            // 8 rows per warp, 8 warps/block
}

// round 13
// speedup vs baseline: 1.1231x; 1.1231x over previous
#include <cuda_runtime.h>
#include <cuda_bf16.h>
#include <cstdint>

#define N_NODES 1000000
#define N_EDGES 8000000
#define NEG_SLOPE 0.01f
#define EPS_F 1e-10f
#define SCAN_NB ((N_NODES + 1023) / 1024)   // 977

// ---------------- static device scratch (no allocation allowed) --------------
__device__ float g_h[(size_t)N_NODES * 64];   // projected h: [node][64], ch0 cols 0-31, ch1 cols 32-63
__device__ int   g_cnt[N_NODES];              // edge count per destination row
__device__ int   g_off[N_NODES + 1];          // CSR offsets (exclusive scan of cnt)
__device__ int   g_cur[N_NODES];              // write cursors (init = off)
__device__ int   g_scol[N_EDGES];             // edge src (col) sorted by destination row
__device__ int   g_bsum[1024];                // scan block sums

// ---------------- helpers ----------------------------------------------------
__device__ __forceinline__ float leaky(float v) { return v > 0.f ? v : NEG_SLOPE * v; }

__device__ __forceinline__ void fma_f32x2(unsigned long long& d,
                                          unsigned long long a,
                                          unsigned long long b) {
    asm("fma.rn.f32x2 %0, %1, %2, %0;" : "+l"(d) : "l"(a), "l"(b));
}
__device__ __forceinline__ unsigned long long pack2(float x, float y) {
    unsigned long long r;
    asm("mov.b64 %0, {%1, %2};" : "=l"(r) : "f"(x), "f"(y));
    return r;
}
__device__ __forceinline__ float2 unpack2(unsigned long long v) {
    float2 r;
    asm("mov.b64 {%0, %1}, %2;" : "=f"(r.x), "=f"(r.y) : "l"(v));
    return r;
}

__device__ __forceinline__ int warp_incl_scan(int v) {
    #pragma unroll
    for (int s = 1; s < 32; s <<= 1) {
        int n = __shfl_up_sync(0xffffffffu, v, s);
        if ((threadIdx.x & 31) >= s) v += n;
    }
    return v;
}

// ---------------- kernel 0: zero counters ------------------------------------
__global__ void zero_kernel() {
    int i = blockIdx.x * blockDim.x + threadIdx.x;
    int stride = gridDim.x * blockDim.x;
    int4* c4 = (int4*)g_cnt;
    int4 z = make_int4(0, 0, 0, 0);
    for (int j = i; j < N_NODES / 4; j += stride) c4[j] = z;
    if (i == 0) g_off[N_NODES] = N_EDGES;
}

// ---------------- kernel 1: projection  h = leaky(ego @ W + b) ---------------
__global__ void project_kernel(const float* __restrict__ ego,
                               const float* __restrict__ W,
                               const float* __restrict__ b) {
    __shared__ unsigned long long Ws2[64 * 32];   // (W0[k][j], W1[k][j])
    __shared__ unsigned long long Bs2[32];
    int t = threadIdx.x;
    for (int idx = t; idx < 64 * 32; idx += blockDim.x) {
        int k = idx >> 5, j = idx & 31;
        Ws2[idx] = pack2(W[k * 32 + j], W[2048 + k * 32 + j]);
    }
    if (t < 32) Bs2[t] = pack2(b[t], b[32 + t]);
    __syncthreads();

    int lane = t & 31;
    int warp = (blockIdx.x * blockDim.x + t) >> 5;
    int nwarps = (gridDim.x * blockDim.x) >> 5;
    for (int base = warp * 4; base < N_NODES; base += nwarps * 4) {
        float2 e0 = *(const float2*)(ego + (size_t)(base + 0) * 64 + 2 * lane);
        float2 e1 = *(const float2*)(ego + (size_t)(base + 1) * 64 + 2 * lane);
        float2 e2 = *(const float2*)(ego + (size_t)(base + 2) * 64 + 2 * lane);
        float2 e3 = *(const float2*)(ego + (size_t)(base + 3) * 64 + 2 * lane);
        unsigned long long a0 = Bs2[lane], a1 = a0, a2 = a0, a3 = a0;
        #pragma unroll
        for (int k = 0; k < 64; k++) {
            unsigned long long wv = Ws2[k * 32 + lane];
            float s0 = __shfl_sync(0xffffffffu, (k & 1) ? e0.y : e0.x, k >> 1);
            float s1 = __shfl_sync(0xffffffffu, (k & 1) ? e1.y : e1.x, k >> 1);
            float s2 = __shfl_sync(0xffffffffu, (k & 1) ? e2.y : e2.x, k >> 1);
            float s3 = __shfl_sync(0xffffffffu, (k & 1) ? e3.y : e3.x, k >> 1);
            fma_f32x2(a0, pack2(s0, s0), wv);
            fma_f32x2(a1, pack2(s1, s1), wv);
            fma_f32x2(a2, pack2(s2, s2), wv);
            fma_f32x2(a3, pack2(s3, s3), wv);
        }
        float2 r0 = unpack2(a0), r1 = unpack2(a1), r2 = unpack2(a2), r3 = unpack2(a3);
        g_h[(size_t)(base + 0) * 64 + lane]      = leaky(r0.x);
        g_h[(size_t)(base + 0) * 64 + 32 + lane] = leaky(r0.y);
        g_h[(size_t)(base + 1) * 64 + lane]      = leaky(r1.x);
        g_h[(size_t)(base + 1) * 64 + 32 + lane] = leaky(r1.y);
        g_h[(size_t)(base + 2) * 64 + lane]      = leaky(r2.x);
        g_h[(size_t)(base + 2) * 64 + 32 + lane] = leaky(r2.y);
        g_h[(size_t)(base + 3) * 64 + lane]      = leaky(r3.x);
        g_h[(size_t)(base + 3) * 64 + 32 + lane] = leaky(r3.y);
    }
}

// ---------------- kernel 2: histogram of destination rows (int4 reads) -------
__global__ void hist_kernel(const int* __restrict__ row) {
    const int4* row4 = (const int4*)row;
    int i = blockIdx.x * blockDim.x + threadIdx.x;
    int stride = gridDim.x * blockDim.x;
    for (; i < N_EDGES / 4; i += stride) {
        int4 v = row4[i];
        atomicAdd(&g_cnt[v.x], 1);
        atomicAdd(&g_cnt[v.y], 1);
        atomicAdd(&g_cnt[v.z], 1);
        atomicAdd(&g_cnt[v.w], 1);
    }
}

// ---------------- kernels 3-5: exclusive scan of g_cnt -> g_off, g_cur -------
__global__ void scan1_kernel() {
    __shared__ int wsum[32];
    int t = threadIdx.x;
    int i = blockIdx.x * 1024 + t;
    int v = (i < N_NODES) ? g_cnt[i] : 0;
    int incl = warp_incl_scan(v);
    int wid = t >> 5, lid = t & 31;
    if (lid == 31) wsum[wid] = incl;
    __syncthreads();
    if (wid == 0) {
        int w = wsum[lid];
        int ws = warp_incl_scan(w);
        wsum[lid] = ws - w;
    }
    __syncthreads();
    int excl = incl - v + wsum[wid];
    if (i < N_NODES) g_off[i] = excl;
    if (t == 1023) g_bsum[blockIdx.x] = excl + v;
}

__global__ void scan2_kernel() {
    __shared__ int wsum[32];
    int t = threadIdx.x;
    int v = (t < SCAN_NB) ? g_bsum[t] : 0;
    int incl = warp_incl_scan(v);
    int wid = t >> 5, lid = t & 31;
    if (lid == 31) wsum[wid] = incl;
    __syncthreads();
    if (wid == 0) {
        int w = wsum[lid];
        int ws = warp_incl_scan(w);
        wsum[lid] = ws - w;
    }
    __syncthreads();
    int excl = incl - v + wsum[wid];
    if (t < SCAN_NB) g_bsum[t] = excl;
}

__global__ void scan3_kernel() {
    int i = blockIdx.x * 1024 + threadIdx.x;
    if (i < N_NODES) {
        int off = g_off[i] + g_bsum[blockIdx.x];
        g_off[i] = off;
        g_cur[i] = off;
    }
}

// ---------------- kernel 6: permute (counting sort of col, int4 reads) -------
__global__ void permute_kernel(const int* __restrict__ row, const int* __restrict__ col) {
    const int4* row4 = (const int4*)row;
    const int4* col4 = (const int4*)col;
    int i = blockIdx.x * blockDim.x + threadIdx.x;
    int stride = gridDim.x * blockDim.x;
    for (; i < N_EDGES / 4; i += stride) {
        int4 r = row4[i];
        int4 c = col4[i];
        g_scol[atomicAdd(&g_cur[r.x], 1)] = c.x;
        g_scol[atomicAdd(&g_cur[r.y], 1)] = c.y;
        g_scol[atomicAdd(&g_cur[r.z], 1)] = c.z;
        g_scol[atomicAdd(&g_cur[r.w], 1)] = c.w;
    }
}

// ---------------- kernel 7: fused logits + softmax + aggregation -------------
// FOUR rows per warp, one 8-lane group per row (proven R11 shape), plus
// BATCHED INDEX LOADING: lane s preloads the edge index for edge b*8+s (one
// coalesced LDG per 8 edges, double-buffered one batch ahead). Each iteration
// obtains its gather address via register shfl -> the scol load drops out of
// the per-iteration prefetch chain (2 serial mem latencies -> 1).
// Warp-uniform trip counts (m, jmax, j all uniform); exhausted groups are
// predicated (ex=0, clamped indices -> L1 hits).
//   out = sum(ex*h_col) / (sum_ex + EPS)
__global__ void __launch_bounds__(256) row_kernel(float* __restrict__ out) {
    int t = blockIdx.x * blockDim.x + threadIdx.x;
    int lane = t & 31;
    int g = lane >> 3;                        // 0..3: row group
    int s = lane & 7;                         // lane within group
    int gbase = g << 3;                       // group's base lane
    int warp = t >> 5;
    int r = warp * 4 + g;                     // this group's row

    int start = g_off[r];
    int deg   = g_off[r + 1] - start;
    // warp-uniform trip count: max degree over the 4 groups
    int m = deg;
    m = max(m, __shfl_xor_sync(0xffffffffu, m, 8));
    m = max(m, __shfl_xor_sync(0xffffffffu, m, 16));

    const float4 hr0 = *(const float4*)(g_h + (size_t)r * 64 + 4 * s);
    const float4 hr1 = *(const float4*)(g_h + (size_t)r * 64 + 32 + 4 * s);

    float se0 = 0.f, se1 = 0.f;
    float4 a0 = make_float4(0.f, 0.f, 0.f, 0.f);
    float4 a1 = make_float4(0.f, 0.f, 0.f, 0.f);

    if (m > 0) {
        int sbase  = (deg > 0) ? start : 0;   // empty groups read g_scol[0]
        int clampv = (deg > 0) ? deg - 1 : 0;
        int nb = (m + 7) >> 3;                // batches of 8 edges (uniform)

        // batch 0 indices: lane s holds index of edge s (clamped)
        int idx_cur = g_scol[sbase + min(s, clampv)];

        // initial gather: edge 0
        int c0 = __shfl_sync(0xffffffffu, idx_cur, gbase);
        float4 hc0 = *(const float4*)(g_h + (size_t)c0 * 64 + 4 * s);
        float4 hc1 = *(const float4*)(g_h + (size_t)c0 * 64 + 32 + 4 * s);

        for (int bchunk = 0; bchunk < nb; bchunk++) {
            int idx_next = 0;
            if (bchunk + 1 < nb)              // load next batch's indices early
                idx_next = g_scol[sbase + min((bchunk + 1) * 8 + s, clampv)];
            int kbase = bchunk << 3;
            int jmax = min(8, m - kbase);     // uniform
            for (int j = 0; j < jmax; j++) {
                int k = kbase + j;
                float4 hn0, hn1;
                if (k + 1 < m) {
                    int srcreg  = (j < 7) ? idx_cur : idx_next;
                    int srclane = (j < 7) ? gbase + j + 1 : gbase;
                    int cn = __shfl_sync(0xffffffffu, srcreg, srclane);
                    hn0 = *(const float4*)(g_h + (size_t)cn * 64 + 4 * s);
                    hn1 = *(const float4*)(g_h + (size_t)cn * 64 + 32 + 4 * s);
                }
                float d0 = hr0.x * hc0.x + hr0.y * hc0.y + hr0.z * hc0.z + hr0.w * hc0.w;
                float d1 = hr1.x * hc1.x + hr1.y * hc1.y + hr1.z * hc1.z + hr1.w * hc1.w;
                d0 += __shfl_xor_sync(0xffffffffu, d0, 4);
                d1 += __shfl_xor_sync(0xffffffffu, d1, 4);
                d0 += __shfl_xor_sync(0xffffffffu, d0, 2);
                d1 += __shfl_xor_sync(0xffffffffu, d1, 2);
                d0 += __shfl_xor_sync(0xffffffffu, d0, 1);
                d1 += __shfl_xor_sync(0xffffffffu, d1, 1);
                bool valid = (k < deg);
                float ex0 = valid ? __expf(leaky(d0)) : 0.f;
                float ex1 = valid ? __expf(leaky(d1)) : 0.f;
                se0 += ex0;
                se1 += ex1;
                a0.x += ex0 * hc0.x; a0.y += ex0 * hc0.y;
                a0.z += ex0 * hc0.z; a0.w += ex0 * hc0.w;
                a1.x += ex1 * hc1.x; a1.y += ex1 * hc1.y;
                a1.z += ex1 * hc1.z; a1.w += ex1 * hc1.w;
                hc0 = hn0; hc1 = hn1;
            }
            idx_cur = idx_next;
        }
    }

    // every lane of the group holds the full dot-reduced sums -> direct write
    float sc0 = 1.0f / (se0 + EPS_F);
    float sc1 = 1.0f / (se1 + EPS_F);
    *(float4*)(out + (size_t)r * 64 + 4 * s) =
        make_float4(a0.x * sc0, a0.y * sc0, a0.z * sc0, a0.w * sc0);
    *(float4*)(out + (size_t)r * 64 + 32 + 4 * s) =
        make_float4(a1.x * sc1, a1.y * sc1, a1.z * sc1, a1.w * sc1);
}

// ---------------- launcher ---------------------------------------------------
// Two-stream fork: project_kernel runs concurrently with the
// zero->hist->scan->permute chain; both join before row_kernel.
static cudaStream_t g_s2 = nullptr;
static cudaEvent_t  g_ev_fork = nullptr;
static cudaEvent_t  g_ev_join = nullptr;

extern "C" void kernel_launch(void* const* d_in, const int* in_sizes, int n_in,
                              void* d_out, int out_size) {
    const float* ego = (const float*)d_in[0];   // [1M, 64] f32
    const float* W   = (const float*)d_in[1];   // [2, 64, 32] f32
    const float* b   = (const float*)d_in[2];   // [2, 1, 32] f32
    const int* row   = (const int*)d_in[3];     // [8M] i32 (destination)
    const int* col   = (const int*)d_in[4];     // [8M] i32 (source)
    float* out       = (float*)d_out;           // [1M, 64] f32

    if (g_s2 == nullptr) {
        cudaStreamCreateWithFlags(&g_s2, cudaStreamNonBlocking);
        cudaEventCreateWithFlags(&g_ev_fork, cudaEventDisableTiming);
        cudaEventCreateWithFlags(&g_ev_join, cudaEventDisableTiming);
    }

    // fork: side stream runs the projection concurrently
    cudaEventRecord(g_ev_fork, 0);
    cudaStreamWaitEvent(g_s2, g_ev_fork, 0);
    project_kernel<<<2048, 256, 0, g_s2>>>(ego, W, b);
    cudaEventRecord(g_ev_join, g_s2);

    // main stream: build sorted-edge structure
    zero_kernel<<<1024, 256>>>();
    hist_kernel<<<4096, 256>>>(row);
    scan1_kernel<<<SCAN_NB, 1024>>>();
    scan2_kernel<<<1, 1024>>>();
    scan3_kernel<<<SCAN_NB, 1024>>>();
    permute_kernel<<<4096, 256>>>(row, col);

    // join: row pass needs both g_h (projection) and g_scol/g_off (sort)
    cudaStreamWaitEvent(0, g_ev_join, 0);
    row_kernel<<<31250, 256>>>(out);            // 4 rows per warp, 8 warps/block
}